// round 7
// baseline (speedup 1.0000x reference)
#include <cuda_runtime.h>

// ---------------- problem constants ----------------
#define BT_   2048      // B*T
#define D_    512
#define HID_  256
#define DK_   100
#define KB_   8
#define R_    64
#define CPER_ 1250
#define NC_   10000

// ---------------- scratch (no allocations allowed) ----------------
__device__ float    g_h [BT_ * HID_];        // 2 MB
__device__ float    g_ur[BT_ * KB_ * R_];    // 4 MB
__device__ unsigned g_sel[320];              // 10000-bit membership bitmap

// ---------------- packed f32x2 helpers (Blackwell dual fp32 pipe) ---------
typedef unsigned long long ull;

__device__ __forceinline__ void fma2(ull& d, ull a, ull b) {
    asm("fma.rn.f32x2 %0, %1, %2, %0;" : "+l"(d) : "l"(a), "l"(b));
}
__device__ __forceinline__ float2 unpack2(ull v) {
    float2 r;
    asm("mov.b64 {%0, %1}, %2;" : "=f"(r.x), "=f"(r.y) : "l"(v));
    return r;
}

// ---------------- zero the selection bitmap ----------------
__global__ void zero_sel_kernel() {
    int t = threadIdx.x;
    if (t < 320) g_sel[t] = 0u;
}

// ---------------- tiled GEMM: C = act(A[M,K] @ B[N,K]^T + bias) ----------
// BM=128, BN=64, BK=32, 256 threads. Per-thread: rows rr..rr+7,
// cols cc+16j (j=0..3). K packed by 2 into f32x2; acc reduced in epilogue.
__global__ __launch_bounds__(256) void gemm_nt_kernel(
    const float* __restrict__ A,
    const float* __restrict__ B, int ldb,
    const float* __restrict__ bias,
    int K, int relu, int dst)
{
    __shared__ float As[128][34];   // even stride: 8B-aligned LDS.64 reads
    __shared__ float Bs[64][34];
    const int m0 = blockIdx.y * 128;
    const int n0 = blockIdx.x * 64;
    const int tid = threadIdx.x;
    const int rr = (tid >> 4) << 3;   // 0..120 step 8
    const int cc = tid & 15;          // cols cc, cc+16, cc+32, cc+48

    ull acc2[8][4];
    #pragma unroll
    for (int i = 0; i < 8; i++)
        #pragma unroll
        for (int j = 0; j < 4; j++) acc2[i][j] = 0ull;   // bits(0,0)

    for (int k0 = 0; k0 < K; k0 += 32) {
        #pragma unroll
        for (int l = 0; l < 4; l++) {               // A tile: 128x32
            int idx = tid + l * 256;
            int row = idx >> 3, c4 = (idx & 7) << 2;
            float4 v = *(const float4*)&A[(size_t)(m0 + row) * D_ + k0 + c4];
            As[row][c4 + 0] = v.x; As[row][c4 + 1] = v.y;
            As[row][c4 + 2] = v.z; As[row][c4 + 3] = v.w;
        }
        #pragma unroll
        for (int l = 0; l < 2; l++) {               // B tile: 64x32
            int idx = tid + l * 256;
            int row = idx >> 3, c4 = (idx & 7) << 2;
            float4 v = *(const float4*)&B[(size_t)(n0 + row) * ldb + k0 + c4];
            Bs[row][c4 + 0] = v.x; Bs[row][c4 + 1] = v.y;
            Bs[row][c4 + 2] = v.z; Bs[row][c4 + 3] = v.w;
        }
        __syncthreads();
        #pragma unroll
        for (int kk2 = 0; kk2 < 16; kk2++) {
            const int kk = kk2 << 1;
            ull b2[4], a2[8];
            #pragma unroll
            for (int j = 0; j < 4; j++)
                b2[j] = *(const ull*)&Bs[cc + 16 * j][kk];
            #pragma unroll
            for (int i = 0; i < 8; i++)
                a2[i] = *(const ull*)&As[rr + i][kk];
            #pragma unroll
            for (int i = 0; i < 8; i++)
                #pragma unroll
                for (int j = 0; j < 4; j++)
                    fma2(acc2[i][j], a2[i], b2[j]);
        }
        __syncthreads();
    }

    float* C   = dst ? g_ur : g_h;
    int    ldc = dst ? (KB_ * R_) : HID_;
    #pragma unroll
    for (int j = 0; j < 4; j++) {
        const int col = n0 + cc + 16 * j;
        float bv = bias ? bias[col] : 0.f;
        #pragma unroll
        for (int i = 0; i < 8; i++) {
            float2 p = unpack2(acc2[i][j]);
            float v = p.x + p.y + bv;
            if (relu) v = fmaxf(v, 0.f);
            C[(size_t)(m0 + rr + i) * ldc + col] = v;
        }
    }
}

// ---------------- candidate scores + stable descending rank -> sel bitmap --
__global__ __launch_bounds__(128) void candidate_kernel(
    const float* __restrict__ W2,
    const float* __restrict__ b2v,
    const int*   __restrict__ idx_base)
{
    __shared__ float hr[HID_];
    __shared__ float sc[DK_];
    const int row = blockIdx.x;
    const int tid = threadIdx.x;

    hr[tid]       = g_h[(size_t)row * HID_ + tid];
    hr[tid + 128] = g_h[(size_t)row * HID_ + tid + 128];
    __syncthreads();

    if (tid < DK_) {
        float s = b2v[tid];
        const float* w = W2 + (size_t)tid * HID_;
        #pragma unroll 8
        for (int i = 0; i < HID_; i++) s = fmaf(hr[i], w[i], s);
        sc[tid] = s;
    }
    __syncthreads();

    if (tid < DK_) {
        const float sv = sc[tid];
        int r = 0;
        // stable descending rank: matches jax.lax.top_k tie-breaking
        for (int u = 0; u < DK_; u++) {
            float su = sc[u];
            r += (su > sv) || (su == sv && u < tid);
        }
        int cls = tid + idx_base[r];
        cls = min(max(cls, 0), NC_ - 1);
        atomicOr(&g_sel[cls >> 5], 1u << (cls & 31));
    }
}

// ---------------- masked low-rank output GEMM --------------------------
// out[m, k*1250 + n] = sel ? (ur[m,k*64:] . V[k,n,:]) + bias : bias
// Grid (20, 16, 8); BM=128, BN=64, BK=32 (2 iters over R=64), f32x2 core.
__global__ __launch_bounds__(256) void svd_out_kernel(
    const float* __restrict__ V,
    const float* __restrict__ bias,
    float* __restrict__ out)
{
    __shared__ float As[128][34];
    __shared__ float Bs[64][34];
    const int k  = blockIdx.z;
    const int m0 = blockIdx.y * 128;
    const int n0 = blockIdx.x * 64;
    const int tid = threadIdx.x;
    const int rr = (tid >> 4) << 3;
    const int cc = tid & 15;
    const float* Vk = V + (size_t)k * CPER_ * R_;

    ull acc2[8][4];
    #pragma unroll
    for (int i = 0; i < 8; i++)
        #pragma unroll
        for (int j = 0; j < 4; j++) acc2[i][j] = 0ull;

    for (int k0 = 0; k0 < R_; k0 += 32) {
        #pragma unroll
        for (int l = 0; l < 4; l++) {               // ur tile: 128x32
            int idx = tid + l * 256;
            int row = idx >> 3, c4 = (idx & 7) << 2;
            float4 v = *(const float4*)&g_ur[(size_t)(m0 + row) * (KB_ * R_) + k * R_ + k0 + c4];
            As[row][c4 + 0] = v.x; As[row][c4 + 1] = v.y;
            As[row][c4 + 2] = v.z; As[row][c4 + 3] = v.w;
        }
        #pragma unroll
        for (int l = 0; l < 2; l++) {               // V tile: 64x32 (row guard)
            int idx = tid + l * 256;
            int row = idx >> 3, c4 = (idx & 7) << 2;
            float4 v = make_float4(0.f, 0.f, 0.f, 0.f);
            if (n0 + row < CPER_)
                v = *(const float4*)&Vk[(size_t)(n0 + row) * R_ + k0 + c4];
            Bs[row][c4 + 0] = v.x; Bs[row][c4 + 1] = v.y;
            Bs[row][c4 + 2] = v.z; Bs[row][c4 + 3] = v.w;
        }
        __syncthreads();
        #pragma unroll
        for (int kk2 = 0; kk2 < 16; kk2++) {
            const int kk = kk2 << 1;
            ull b2[4], a2[8];
            #pragma unroll
            for (int j = 0; j < 4; j++)
                b2[j] = *(const ull*)&Bs[cc + 16 * j][kk];
            #pragma unroll
            for (int i = 0; i < 8; i++)
                a2[i] = *(const ull*)&As[rr + i][kk];
            #pragma unroll
            for (int i = 0; i < 8; i++)
                #pragma unroll
                for (int j = 0; j < 4; j++)
                    fma2(acc2[i][j], a2[i], b2[j]);
        }
        __syncthreads();
    }

    #pragma unroll
    for (int j = 0; j < 4; j++) {
        const int col = n0 + cc + 16 * j;
        if (col >= CPER_) continue;
        const int cg = k * CPER_ + col;
        const float mf = (float)((g_sel[cg >> 5] >> (cg & 31)) & 1u);
        const float bs = bias[cg];
        #pragma unroll
        for (int i = 0; i < 8; i++) {
            float2 p = unpack2(acc2[i][j]);
            out[(size_t)(m0 + rr + i) * NC_ + cg] = fmaf(mf, p.x + p.y, bs);
        }
    }
}

// ---------------- launch ----------------
extern "C" void kernel_launch(void* const* d_in, const int* in_sizes, int n_in,
                              void* d_out, int out_size)
{
    const float* x        = (const float*)d_in[0];
    const float* W1       = (const float*)d_in[1];
    const float* b1       = (const float*)d_in[2];
    const float* W2       = (const float*)d_in[3];
    const float* b2       = (const float*)d_in[4];
    const float* U        = (const float*)d_in[5];
    const float* V        = (const float*)d_in[6];
    const float* bias     = (const float*)d_in[7];
    const int*   idx_base = (const int*)d_in[8];
    float* out = (float*)d_out;

    (void)in_sizes; (void)n_in; (void)out_size;

    zero_sel_kernel<<<1, 512>>>();

    // h = relu(x @ W1^T + b1)   [2048, 256]
    gemm_nt_kernel<<<dim3(HID_ / 64, BT_ / 128), 256>>>(
        x, W1, D_, b1, D_, /*relu=*/1, /*dst=*/0);

    // scores + ranks -> sel bitmap
    candidate_kernel<<<BT_, 128>>>(W2, b2, idx_base);

    // ur = x @ U^T   (U flattened [512, 512])   [2048, 512]
    gemm_nt_kernel<<<dim3((KB_ * R_) / 64, BT_ / 128), 256>>>(
        x, U, D_, nullptr, D_, /*relu=*/0, /*dst=*/1);

    // out = mask(ur_k @ V_k^T) + bias
    svd_out_kernel<<<dim3(20, BT_ / 128, KB_), 256>>>(V, bias, out);
}

// round 10
// speedup vs baseline: 1.1131x; 1.1131x over previous
#include <cuda_runtime.h>
#include <cuda_bf16.h>
#include <cstdint>

// ---------------- problem constants ----------------
#define BT_   2048      // B*T
#define D_    512
#define HID_  256
#define DK_   100
#define KB_   8
#define R_    64
#define CPER_ 1250
#define NC_   10000

// ---------------- scratch (no allocations allowed) ----------------
__device__ float         g_h [BT_ * HID_];
__device__ float         g_ur[BT_ * KB_ * R_];
__device__ unsigned      g_sel[320];
__device__ __nv_bfloat16 g_ur_hi[BT_ * KB_ * R_];
__device__ __nv_bfloat16 g_ur_lo[BT_ * KB_ * R_];
__device__ __nv_bfloat16 g_v_hi[NC_ * R_];
__device__ __nv_bfloat16 g_v_lo[NC_ * R_];

// ---------------- zero the selection bitmap ----------------
__global__ void zero_sel_kernel() {
    int t = threadIdx.x;
    if (t < 320) g_sel[t] = 0u;
}

// ---------------- tiled fp32 GEMM: C = act(A[M,K] @ B[N,K]^T + bias) -----
__global__ __launch_bounds__(256) void gemm_nt_kernel(
    const float* __restrict__ A,
    const float* __restrict__ B, int ldb,
    const float* __restrict__ bias,
    int K, int relu, int dst)
{
    __shared__ float As[128][33];
    __shared__ float Bs[64][33];
    const int m0 = blockIdx.y * 128;
    const int n0 = blockIdx.x * 64;
    const int tid = threadIdx.x;
    const int rr = (tid >> 4) << 3;
    const int cc = (tid & 15) << 2;

    float acc[8][4];
    #pragma unroll
    for (int i = 0; i < 8; i++)
        #pragma unroll
        for (int j = 0; j < 4; j++) acc[i][j] = 0.f;

    for (int k0 = 0; k0 < K; k0 += 32) {
        #pragma unroll
        for (int l = 0; l < 4; l++) {
            int idx = tid + l * 256;
            int row = idx >> 3, c4 = (idx & 7) << 2;
            float4 v = *(const float4*)&A[(size_t)(m0 + row) * D_ + k0 + c4];
            As[row][c4 + 0] = v.x; As[row][c4 + 1] = v.y;
            As[row][c4 + 2] = v.z; As[row][c4 + 3] = v.w;
        }
        #pragma unroll
        for (int l = 0; l < 2; l++) {
            int idx = tid + l * 256;
            int row = idx >> 3, c4 = (idx & 7) << 2;
            float4 v = *(const float4*)&B[(size_t)(n0 + row) * ldb + k0 + c4];
            Bs[row][c4 + 0] = v.x; Bs[row][c4 + 1] = v.y;
            Bs[row][c4 + 2] = v.z; Bs[row][c4 + 3] = v.w;
        }
        __syncthreads();
        #pragma unroll
        for (int kk = 0; kk < 32; kk++) {
            float a[8], b[4];
            #pragma unroll
            for (int i = 0; i < 8; i++) a[i] = As[rr + i][kk];
            #pragma unroll
            for (int j = 0; j < 4; j++) b[j] = Bs[cc + j][kk];
            #pragma unroll
            for (int i = 0; i < 8; i++)
                #pragma unroll
                for (int j = 0; j < 4; j++)
                    acc[i][j] = fmaf(a[i], b[j], acc[i][j]);
        }
        __syncthreads();
    }

    float* C   = dst ? g_ur : g_h;
    int    ldc = dst ? (KB_ * R_) : HID_;
    float4 bv = make_float4(0.f, 0.f, 0.f, 0.f);
    if (bias) bv = make_float4(bias[n0 + cc], bias[n0 + cc + 1],
                               bias[n0 + cc + 2], bias[n0 + cc + 3]);
    #pragma unroll
    for (int i = 0; i < 8; i++) {
        float4 v;
        v.x = acc[i][0] + bv.x; v.y = acc[i][1] + bv.y;
        v.z = acc[i][2] + bv.z; v.w = acc[i][3] + bv.w;
        if (relu) {
            v.x = fmaxf(v.x, 0.f); v.y = fmaxf(v.y, 0.f);
            v.z = fmaxf(v.z, 0.f); v.w = fmaxf(v.w, 0.f);
        }
        *(float4*)&C[(size_t)(m0 + rr + i) * ldc + n0 + cc] = v;
    }
}

// ---------------- candidate scores + stable descending rank -> sel bitmap -
__global__ __launch_bounds__(128) void candidate_kernel(
    const float* __restrict__ W2,
    const float* __restrict__ b2v,
    const int*   __restrict__ idx_base)
{
    __shared__ float hr[HID_];
    __shared__ float sc[DK_];
    const int row = blockIdx.x;
    const int tid = threadIdx.x;

    hr[tid]       = g_h[(size_t)row * HID_ + tid];
    hr[tid + 128] = g_h[(size_t)row * HID_ + tid + 128];
    __syncthreads();

    if (tid < DK_) {
        float s = b2v[tid];
        const float* w = W2 + (size_t)tid * HID_;
        #pragma unroll 8
        for (int i = 0; i < HID_; i++) s = fmaf(hr[i], w[i], s);
        sc[tid] = s;
    }
    __syncthreads();

    if (tid < DK_) {
        const float sv = sc[tid];
        int r = 0;
        for (int u = 0; u < DK_; u++) {
            float su = sc[u];
            r += (su > sv) || (su == sv && u < tid);
        }
        int cls = tid + idx_base[r];
        cls = min(max(cls, 0), NC_ - 1);
        atomicOr(&g_sel[cls >> 5], 1u << (cls & 31));
    }
}

// ---------------- bf16 hi/lo split conversions ---------------------------
__global__ __launch_bounds__(256) void split_ur_kernel() {
    int i = blockIdx.x * 256 + threadIdx.x;      // exactly BT_*KB_*R_ threads
    float v = g_ur[i];
    __nv_bfloat16 h = __float2bfloat16(v);
    g_ur_hi[i] = h;
    g_ur_lo[i] = __float2bfloat16(v - __bfloat162float(h));
}
__global__ __launch_bounds__(256) void split_v_kernel(const float* __restrict__ V) {
    int i = blockIdx.x * 256 + threadIdx.x;
    if (i < NC_ * R_) {
        float v = V[i];
        __nv_bfloat16 h = __float2bfloat16(v);
        g_v_hi[i] = h;
        g_v_lo[i] = __float2bfloat16(v - __bfloat162float(h));
    }
}

// ---------------- HMMA masked output GEMM --------------------------------
// D[128,64] = Ahi·Bhi^T + Ahi·Blo^T + Alo·Bhi^T  via mma.sync m16n8k16 bf16
// out[m, k*1250+n] = bias + mask * D
// smem stride 72 bf16 (144B): fragment LDS.32 pattern 4r+q -> conflict-free.
#define ASTR 72
#define SMO_AH 0
#define SMO_AL (128 * ASTR * 2)                 // 18432
#define SMO_BH (2 * 128 * ASTR * 2)             // 36864
#define SMO_BL (2 * 128 * ASTR * 2 + 64 * ASTR * 2)
#define SMO_BIAS (2 * 128 * ASTR * 2 + 2 * 64 * ASTR * 2)   // 55296
#define SMO_MASK (SMO_BIAS + 256)
#define SMO_TOTAL (SMO_MASK + 256)              // 55808

__device__ __forceinline__ void mma16816(float* d, const uint32_t* a, const uint32_t* b) {
    asm volatile(
        "mma.sync.aligned.m16n8k16.row.col.f32.bf16.bf16.f32 "
        "{%0,%1,%2,%3}, {%4,%5,%6,%7}, {%8,%9}, {%0,%1,%2,%3};"
        : "+f"(d[0]), "+f"(d[1]), "+f"(d[2]), "+f"(d[3])
        : "r"(a[0]), "r"(a[1]), "r"(a[2]), "r"(a[3]), "r"(b[0]), "r"(b[1]));
}

__global__ __launch_bounds__(128) void svd_out_mma(
    const float* __restrict__ bias,
    float* __restrict__ out)
{
    extern __shared__ char smem[];
    const int tid  = threadIdx.x;
    const int wid  = tid >> 5;
    const int lane = tid & 31;
    const int k  = blockIdx.z;
    const int m0 = blockIdx.y * 128;
    const int n0 = blockIdx.x * 64;

    __nv_bfloat16* Ah = (__nv_bfloat16*)(smem + SMO_AH);
    __nv_bfloat16* Al = (__nv_bfloat16*)(smem + SMO_AL);
    __nv_bfloat16* Bh = (__nv_bfloat16*)(smem + SMO_BH);
    __nv_bfloat16* Bl = (__nv_bfloat16*)(smem + SMO_BL);
    float* sbias = (float*)(smem + SMO_BIAS);
    float* smask = (float*)(smem + SMO_MASK);

    // stage A (ur hi/lo): one 64-bf16 row per thread, 8 x uint4
    {
        const size_t go = (size_t)(m0 + tid) * (KB_ * R_) + k * R_;
        #pragma unroll
        for (int ch = 0; ch < 8; ch++) {
            *(uint4*)&Ah[tid * ASTR + ch * 8] = *(const uint4*)&g_ur_hi[go + ch * 8];
            *(uint4*)&Al[tid * ASTR + ch * 8] = *(const uint4*)&g_ur_lo[go + ch * 8];
        }
    }
    // stage B (V hi/lo): half row per thread (32 bf16 = 4 x uint4), OOB rows = 0
    {
        const int row = tid >> 1, half = (tid & 1) * 32;
        const bool ok = (n0 + row) < CPER_;
        const size_t go = (size_t)(k * CPER_ + n0 + row) * R_ + half;
        #pragma unroll
        for (int ch = 0; ch < 4; ch++) {
            uint4 vh = make_uint4(0u, 0u, 0u, 0u), vl = vh;
            if (ok) {
                vh = *(const uint4*)&g_v_hi[go + ch * 8];
                vl = *(const uint4*)&g_v_lo[go + ch * 8];
            }
            *(uint4*)&Bh[row * ASTR + half + ch * 8] = vh;
            *(uint4*)&Bl[row * ASTR + half + ch * 8] = vl;
        }
    }
    if (tid < 64) {
        int col = n0 + tid;
        float bv = 0.f, mv = 0.f;
        if (col < CPER_) {
            int cg = k * CPER_ + col;
            bv = bias[cg];
            mv = (float)((g_sel[cg >> 5] >> (cg & 31)) & 1u);
        }
        sbias[tid] = bv;
        smask[tid] = mv;
    }
    __syncthreads();

    // per-warp: rows wm..wm+31 (2 m16 tiles) x 64 cols (8 n8 tiles)
    const int wm = wid * 32;
    const int g  = lane >> 2;        // 0..7
    const int q  = lane & 3;         // 0..3
    float acc[2][8][4];
    #pragma unroll
    for (int mt = 0; mt < 2; mt++)
        #pragma unroll
        for (int nt = 0; nt < 8; nt++)
            #pragma unroll
            for (int e = 0; e < 4; e++) acc[mt][nt][e] = 0.f;

    const __nv_bfloat16* Ap[3] = { Ah, Ah, Al };
    const __nv_bfloat16* Bp[3] = { Bh, Bl, Bh };
    #pragma unroll
    for (int p = 0; p < 3; p++) {
        const __nv_bfloat16* As = Ap[p];
        const __nv_bfloat16* Bs = Bp[p];
        #pragma unroll
        for (int ks = 0; ks < 4; ks++) {
            const int kc = ks * 16 + q * 2;
            uint32_t a[2][4], b[8][2];
            #pragma unroll
            for (int mt = 0; mt < 2; mt++) {
                const int r = wm + mt * 16 + g;
                a[mt][0] = *(const uint32_t*)&As[(r    ) * ASTR + kc    ];
                a[mt][1] = *(const uint32_t*)&As[(r + 8) * ASTR + kc    ];
                a[mt][2] = *(const uint32_t*)&As[(r    ) * ASTR + kc + 8];
                a[mt][3] = *(const uint32_t*)&As[(r + 8) * ASTR + kc + 8];
            }
            #pragma unroll
            for (int nt = 0; nt < 8; nt++) {
                const int n = nt * 8 + g;
                b[nt][0] = *(const uint32_t*)&Bs[n * ASTR + kc    ];
                b[nt][1] = *(const uint32_t*)&Bs[n * ASTR + kc + 8];
            }
            #pragma unroll
            for (int mt = 0; mt < 2; mt++)
                #pragma unroll
                for (int nt = 0; nt < 8; nt++)
                    mma16816(acc[mt][nt], a[mt], b[nt]);
        }
    }

    // epilogue: mask*D + bias, float2 stores (always 8B-aligned)
    const int vn = (CPER_ - n0 < 64) ? (CPER_ - n0) : 64;   // even
    const size_t cgbase = (size_t)k * CPER_ + n0;
    #pragma unroll
    for (int nt = 0; nt < 8; nt++) {
        const int cl = nt * 8 + q * 2;                       // local col, even
        if (cl >= vn) continue;
        const float b0 = sbias[cl], b1 = sbias[cl + 1];
        const float q0 = smask[cl], q1 = smask[cl + 1];
        #pragma unroll
        for (int mt = 0; mt < 2; mt++) {
            const int r0 = m0 + wm + mt * 16 + g;
            float2 v0, v1;
            v0.x = fmaf(q0, acc[mt][nt][0], b0);
            v0.y = fmaf(q1, acc[mt][nt][1], b1);
            v1.x = fmaf(q0, acc[mt][nt][2], b0);
            v1.y = fmaf(q1, acc[mt][nt][3], b1);
            *(float2*)&out[(size_t)r0 * NC_ + cgbase + cl]       = v0;
            *(float2*)&out[(size_t)(r0 + 8) * NC_ + cgbase + cl] = v1;
        }
    }
}

// ---------------- launch ----------------
extern "C" void kernel_launch(void* const* d_in, const int* in_sizes, int n_in,
                              void* d_out, int out_size)
{
    const float* x        = (const float*)d_in[0];
    const float* W1       = (const float*)d_in[1];
    const float* b1       = (const float*)d_in[2];
    const float* W2       = (const float*)d_in[3];
    const float* b2       = (const float*)d_in[4];
    const float* U        = (const float*)d_in[5];
    const float* V        = (const float*)d_in[6];
    const float* bias     = (const float*)d_in[7];
    const int*   idx_base = (const int*)d_in[8];
    float* out = (float*)d_out;

    (void)in_sizes; (void)n_in; (void)out_size;

    cudaFuncSetAttribute(svd_out_mma,
                         cudaFuncAttributeMaxDynamicSharedMemorySize, SMO_TOTAL);

    zero_sel_kernel<<<1, 512>>>();

    // h = relu(x @ W1^T + b1)
    gemm_nt_kernel<<<dim3(HID_ / 64, BT_ / 128), 256>>>(
        x, W1, D_, b1, D_, 1, 0);

    // scores + stable ranks -> sel bitmap (bit-exact fp32 path)
    candidate_kernel<<<BT_, 128>>>(W2, b2, idx_base);

    // ur = x @ U^T
    gemm_nt_kernel<<<dim3((KB_ * R_) / 64, BT_ / 128), 256>>>(
        x, U, D_, nullptr, D_, 0, 1);

    // bf16 hi/lo splits for tensor-core consumption
    split_ur_kernel<<<(BT_ * KB_ * R_) / 256, 256>>>();
    split_v_kernel<<<(NC_ * R_ + 255) / 256, 256>>>(V);

    // masked low-rank output via mma.sync bf16 (split, 3 products)
    svd_out_mma<<<dim3(20, BT_ / 128, KB_), 128, SMO_TOTAL>>>(bias, out);
}

// round 11
// speedup vs baseline: 1.1198x; 1.0060x over previous
#include <cuda_runtime.h>
#include <cuda_bf16.h>
#include <cstdint>

// ---------------- problem constants ----------------
#define BT_   2048      // B*T
#define D_    512
#define HID_  256
#define DK_   100
#define KB_   8
#define R_    64
#define CPER_ 1250
#define NC_   10000

// ---------------- scratch (no allocations allowed) ----------------
__device__ float         g_h [BT_ * HID_];
__device__ float         g_ur[BT_ * KB_ * R_];
__device__ unsigned      g_sel[320];
__device__ __nv_bfloat16 g_ur_hi[BT_ * KB_ * R_];
__device__ __nv_bfloat16 g_ur_lo[BT_ * KB_ * R_];
__device__ __nv_bfloat16 g_v_hi[NC_ * R_];
__device__ __nv_bfloat16 g_v_lo[NC_ * R_];

// ---------------- zero the selection bitmap ----------------
__global__ void zero_sel_kernel() {
    int t = threadIdx.x;
    if (t < 320) g_sel[t] = 0u;
}

// ---------------- tiled fp32 GEMM: C = act(A[M,K] @ B[N,K]^T + bias) -----
__global__ __launch_bounds__(256) void gemm_nt_kernel(
    const float* __restrict__ A,
    const float* __restrict__ B, int ldb,
    const float* __restrict__ bias,
    int K, int relu, int dst)
{
    __shared__ float As[128][33];
    __shared__ float Bs[64][33];
    const int m0 = blockIdx.y * 128;
    const int n0 = blockIdx.x * 64;
    const int tid = threadIdx.x;
    const int rr = (tid >> 4) << 3;
    const int cc = (tid & 15) << 2;

    float acc[8][4];
    #pragma unroll
    for (int i = 0; i < 8; i++)
        #pragma unroll
        for (int j = 0; j < 4; j++) acc[i][j] = 0.f;

    for (int k0 = 0; k0 < K; k0 += 32) {
        #pragma unroll
        for (int l = 0; l < 4; l++) {
            int idx = tid + l * 256;
            int row = idx >> 3, c4 = (idx & 7) << 2;
            float4 v = *(const float4*)&A[(size_t)(m0 + row) * D_ + k0 + c4];
            As[row][c4 + 0] = v.x; As[row][c4 + 1] = v.y;
            As[row][c4 + 2] = v.z; As[row][c4 + 3] = v.w;
        }
        #pragma unroll
        for (int l = 0; l < 2; l++) {
            int idx = tid + l * 256;
            int row = idx >> 3, c4 = (idx & 7) << 2;
            float4 v = *(const float4*)&B[(size_t)(n0 + row) * ldb + k0 + c4];
            Bs[row][c4 + 0] = v.x; Bs[row][c4 + 1] = v.y;
            Bs[row][c4 + 2] = v.z; Bs[row][c4 + 3] = v.w;
        }
        __syncthreads();
        #pragma unroll
        for (int kk = 0; kk < 32; kk++) {
            float a[8], b[4];
            #pragma unroll
            for (int i = 0; i < 8; i++) a[i] = As[rr + i][kk];
            #pragma unroll
            for (int j = 0; j < 4; j++) b[j] = Bs[cc + j][kk];
            #pragma unroll
            for (int i = 0; i < 8; i++)
                #pragma unroll
                for (int j = 0; j < 4; j++)
                    acc[i][j] = fmaf(a[i], b[j], acc[i][j]);
        }
        __syncthreads();
    }

    float* C   = dst ? g_ur : g_h;
    int    ldc = dst ? (KB_ * R_) : HID_;
    float4 bv = make_float4(0.f, 0.f, 0.f, 0.f);
    if (bias) bv = make_float4(bias[n0 + cc], bias[n0 + cc + 1],
                               bias[n0 + cc + 2], bias[n0 + cc + 3]);
    #pragma unroll
    for (int i = 0; i < 8; i++) {
        float4 v;
        v.x = acc[i][0] + bv.x; v.y = acc[i][1] + bv.y;
        v.z = acc[i][2] + bv.z; v.w = acc[i][3] + bv.w;
        if (relu) {
            v.x = fmaxf(v.x, 0.f); v.y = fmaxf(v.y, 0.f);
            v.z = fmaxf(v.z, 0.f); v.w = fmaxf(v.w, 0.f);
        }
        *(float4*)&C[(size_t)(m0 + rr + i) * ldc + n0 + cc] = v;
    }
}

// ---------------- candidate scores + stable descending rank -> sel bitmap -
__global__ __launch_bounds__(128) void candidate_kernel(
    const float* __restrict__ W2,
    const float* __restrict__ b2v,
    const int*   __restrict__ idx_base)
{
    __shared__ float hr[HID_];
    __shared__ float sc[DK_];
    const int row = blockIdx.x;
    const int tid = threadIdx.x;

    hr[tid]       = g_h[(size_t)row * HID_ + tid];
    hr[tid + 128] = g_h[(size_t)row * HID_ + tid + 128];
    __syncthreads();

    if (tid < DK_) {
        float s = b2v[tid];
        const float* w = W2 + (size_t)tid * HID_;
        #pragma unroll 8
        for (int i = 0; i < HID_; i++) s = fmaf(hr[i], w[i], s);
        sc[tid] = s;
    }
    __syncthreads();

    if (tid < DK_) {
        const float sv = sc[tid];
        int r = 0;
        for (int u = 0; u < DK_; u++) {
            float su = sc[u];
            r += (su > sv) || (su == sv && u < tid);
        }
        int cls = tid + idx_base[r];
        cls = min(max(cls, 0), NC_ - 1);
        atomicOr(&g_sel[cls >> 5], 1u << (cls & 31));
    }
}

// ---------------- bf16 hi/lo split conversions ---------------------------
__global__ __launch_bounds__(256) void split_ur_kernel() {
    int i = blockIdx.x * 256 + threadIdx.x;      // exactly BT_*KB_*R_ threads
    float v = g_ur[i];
    __nv_bfloat16 h = __float2bfloat16(v);
    g_ur_hi[i] = h;
    g_ur_lo[i] = __float2bfloat16(v - __bfloat162float(h));
}
__global__ __launch_bounds__(256) void split_v_kernel(const float* __restrict__ V) {
    int i = blockIdx.x * 256 + threadIdx.x;
    if (i < NC_ * R_) {
        float v = V[i];
        __nv_bfloat16 h = __float2bfloat16(v);
        g_v_hi[i] = h;
        g_v_lo[i] = __float2bfloat16(v - __bfloat162float(h));
    }
}

// ---------------- HMMA masked output GEMM --------------------------------
// D[128,64] = Ahi·Bhi^T + Ahi·Blo^T + Alo·Bhi^T  via mma.sync m16n8k16 bf16
// out[m, k*1250+n] = bias + mask * D
// smem stride 72 bf16 (144B): fragment LDS.32 pattern 4r+q -> conflict-free.
#define ASTR 72
#define SMO_AH 0
#define SMO_AL (128 * ASTR * 2)                 // 18432
#define SMO_BH (2 * 128 * ASTR * 2)             // 36864
#define SMO_BL (2 * 128 * ASTR * 2 + 64 * ASTR * 2)
#define SMO_BIAS (2 * 128 * ASTR * 2 + 2 * 64 * ASTR * 2)   // 55296
#define SMO_MASK (SMO_BIAS + 256)
#define SMO_TOTAL (SMO_MASK + 256)              // 55808

__device__ __forceinline__ void mma16816(float* d, const uint32_t* a, const uint32_t* b) {
    asm volatile(
        "mma.sync.aligned.m16n8k16.row.col.f32.bf16.bf16.f32 "
        "{%0,%1,%2,%3}, {%4,%5,%6,%7}, {%8,%9}, {%0,%1,%2,%3};"
        : "+f"(d[0]), "+f"(d[1]), "+f"(d[2]), "+f"(d[3])
        : "r"(a[0]), "r"(a[1]), "r"(a[2]), "r"(a[3]), "r"(b[0]), "r"(b[1]));
}

__global__ __launch_bounds__(128) void svd_out_mma(
    const float* __restrict__ bias,
    float* __restrict__ out)
{
    extern __shared__ char smem[];
    const int tid  = threadIdx.x;
    const int wid  = tid >> 5;
    const int lane = tid & 31;
    const int k  = blockIdx.z;
    const int m0 = blockIdx.y * 128;
    const int n0 = blockIdx.x * 64;

    __nv_bfloat16* Ah = (__nv_bfloat16*)(smem + SMO_AH);
    __nv_bfloat16* Al = (__nv_bfloat16*)(smem + SMO_AL);
    __nv_bfloat16* Bh = (__nv_bfloat16*)(smem + SMO_BH);
    __nv_bfloat16* Bl = (__nv_bfloat16*)(smem + SMO_BL);
    float* sbias = (float*)(smem + SMO_BIAS);
    float* smask = (float*)(smem + SMO_MASK);

    // stage A (ur hi/lo): one 64-bf16 row per thread, 8 x uint4
    {
        const size_t go = (size_t)(m0 + tid) * (KB_ * R_) + k * R_;
        #pragma unroll
        for (int ch = 0; ch < 8; ch++) {
            *(uint4*)&Ah[tid * ASTR + ch * 8] = *(const uint4*)&g_ur_hi[go + ch * 8];
            *(uint4*)&Al[tid * ASTR + ch * 8] = *(const uint4*)&g_ur_lo[go + ch * 8];
        }
    }
    // stage B (V hi/lo): half row per thread (32 bf16 = 4 x uint4), OOB rows = 0
    {
        const int row = tid >> 1, half = (tid & 1) * 32;
        const bool ok = (n0 + row) < CPER_;
        const size_t go = (size_t)(k * CPER_ + n0 + row) * R_ + half;
        #pragma unroll
        for (int ch = 0; ch < 4; ch++) {
            uint4 vh = make_uint4(0u, 0u, 0u, 0u), vl = vh;
            if (ok) {
                vh = *(const uint4*)&g_v_hi[go + ch * 8];
                vl = *(const uint4*)&g_v_lo[go + ch * 8];
            }
            *(uint4*)&Bh[row * ASTR + half + ch * 8] = vh;
            *(uint4*)&Bl[row * ASTR + half + ch * 8] = vl;
        }
    }
    if (tid < 64) {
        int col = n0 + tid;
        float bv = 0.f, mv = 0.f;
        if (col < CPER_) {
            int cg = k * CPER_ + col;
            bv = bias[cg];
            mv = (float)((g_sel[cg >> 5] >> (cg & 31)) & 1u);
        }
        sbias[tid] = bv;
        smask[tid] = mv;
    }
    __syncthreads();

    // per-warp: rows wm..wm+31 (2 m16 tiles) x 64 cols (8 n8 tiles)
    const int wm = wid * 32;
    const int g  = lane >> 2;        // 0..7
    const int q  = lane & 3;         // 0..3
    float acc[2][8][4];
    #pragma unroll
    for (int mt = 0; mt < 2; mt++)
        #pragma unroll
        for (int nt = 0; nt < 8; nt++)
            #pragma unroll
            for (int e = 0; e < 4; e++) acc[mt][nt][e] = 0.f;

    const __nv_bfloat16* Ap[3] = { Ah, Ah, Al };
    const __nv_bfloat16* Bp[3] = { Bh, Bl, Bh };
    #pragma unroll
    for (int p = 0; p < 3; p++) {
        const __nv_bfloat16* As = Ap[p];
        const __nv_bfloat16* Bs = Bp[p];
        #pragma unroll
        for (int ks = 0; ks < 4; ks++) {
            const int kc = ks * 16 + q * 2;
            uint32_t a[2][4], b[8][2];
            #pragma unroll
            for (int mt = 0; mt < 2; mt++) {
                const int r = wm + mt * 16 + g;
                a[mt][0] = *(const uint32_t*)&As[(r    ) * ASTR + kc    ];
                a[mt][1] = *(const uint32_t*)&As[(r + 8) * ASTR + kc    ];
                a[mt][2] = *(const uint32_t*)&As[(r    ) * ASTR + kc + 8];
                a[mt][3] = *(const uint32_t*)&As[(r + 8) * ASTR + kc + 8];
            }
            #pragma unroll
            for (int nt = 0; nt < 8; nt++) {
                const int n = nt * 8 + g;
                b[nt][0] = *(const uint32_t*)&Bs[n * ASTR + kc    ];
                b[nt][1] = *(const uint32_t*)&Bs[n * ASTR + kc + 8];
            }
            #pragma unroll
            for (int mt = 0; mt < 2; mt++)
                #pragma unroll
                for (int nt = 0; nt < 8; nt++)
                    mma16816(acc[mt][nt], a[mt], b[nt]);
        }
    }

    // epilogue: mask*D + bias, float2 stores (always 8B-aligned)
    const int vn = (CPER_ - n0 < 64) ? (CPER_ - n0) : 64;   // even
    const size_t cgbase = (size_t)k * CPER_ + n0;
    #pragma unroll
    for (int nt = 0; nt < 8; nt++) {
        const int cl = nt * 8 + q * 2;                       // local col, even
        if (cl >= vn) continue;
        const float b0 = sbias[cl], b1 = sbias[cl + 1];
        const float q0 = smask[cl], q1 = smask[cl + 1];
        #pragma unroll
        for (int mt = 0; mt < 2; mt++) {
            const int r0 = m0 + wm + mt * 16 + g;
            float2 v0, v1;
            v0.x = fmaf(q0, acc[mt][nt][0], b0);
            v0.y = fmaf(q1, acc[mt][nt][1], b1);
            v1.x = fmaf(q0, acc[mt][nt][2], b0);
            v1.y = fmaf(q1, acc[mt][nt][3], b1);
            *(float2*)&out[(size_t)r0 * NC_ + cgbase + cl]       = v0;
            *(float2*)&out[(size_t)(r0 + 8) * NC_ + cgbase + cl] = v1;
        }
    }
}

// ---------------- launch ----------------
extern "C" void kernel_launch(void* const* d_in, const int* in_sizes, int n_in,
                              void* d_out, int out_size)
{
    const float* x        = (const float*)d_in[0];
    const float* W1       = (const float*)d_in[1];
    const float* b1       = (const float*)d_in[2];
    const float* W2       = (const float*)d_in[3];
    const float* b2       = (const float*)d_in[4];
    const float* U        = (const float*)d_in[5];
    const float* V        = (const float*)d_in[6];
    const float* bias     = (const float*)d_in[7];
    const int*   idx_base = (const int*)d_in[8];
    float* out = (float*)d_out;

    (void)in_sizes; (void)n_in; (void)out_size;

    cudaFuncSetAttribute(svd_out_mma,
                         cudaFuncAttributeMaxDynamicSharedMemorySize, SMO_TOTAL);

    zero_sel_kernel<<<1, 512>>>();

    // h = relu(x @ W1^T + b1)
    gemm_nt_kernel<<<dim3(HID_ / 64, BT_ / 128), 256>>>(
        x, W1, D_, b1, D_, 1, 0);

    // scores + stable ranks -> sel bitmap (bit-exact fp32 path)
    candidate_kernel<<<BT_, 128>>>(W2, b2, idx_base);

    // ur = x @ U^T
    gemm_nt_kernel<<<dim3((KB_ * R_) / 64, BT_ / 128), 256>>>(
        x, U, D_, nullptr, D_, 0, 1);

    // bf16 hi/lo splits for tensor-core consumption
    split_ur_kernel<<<(BT_ * KB_ * R_) / 256, 256>>>();
    split_v_kernel<<<(NC_ * R_ + 255) / 256, 256>>>(V);

    // masked low-rank output via mma.sync bf16 (split, 3 products)
    svd_out_mma<<<dim3(20, BT_ / 128, KB_), 128, SMO_TOTAL>>>(bias, out);
}